// round 1
// baseline (speedup 1.0000x reference)
#include <cuda_runtime.h>
#include <math.h>

// Problem constants
#define B  64
#define T  2048
#define I  128
#define H  256

// Tiling: 16 batch-groups x 8 hidden-slices = 128 CTAs (1 per SM)
#define NG 16      // batch groups
#define NS 8       // hidden slices per group
#define NB 4       // batches per group  (NG*NB = B)
#define NU 32      // hidden units per slice (NS*NU = H)
#define THREADS 256
#define KSPL 8     // K-split factor (warps)

// SMEM layout (in floats)
#define SZ_W      (3*384*32)                 // 36864: [gate][k(combined 384)][u(32)] xor-swizzled
#define OFF_W     0
#define OFF_BR    (OFF_W + SZ_W)
#define OFF_BZ    (OFF_BR + 32)
#define OFF_BIN   (OFF_BZ + 32)
#define OFF_BHN   (OFF_BIN + 32)
#define OFF_X     (OFF_BHN + 32)             // double-buffered x_t: 2*NB*I = 1024
#define OFF_H     (OFF_X + 2*NB*I)           // h_{t-1}: NB*H = 1024
#define OFF_PX    (OFF_H + NB*H)             // x-phase partials: 3*NB*KSPL*32 = 3072
#define OFF_PH    (OFF_PX + 3*NB*KSPL*32)    // h-phase partials: 3072
#define SMEM_FLOATS (OFF_PH + 3*NB*KSPL*32)  // 45184 floats
#define SMEM_BYTES  (SMEM_FLOATS * 4)        // 180736 bytes

__device__ unsigned g_flags[NG];             // zero-init; reset by out kernel each launch

__device__ __forceinline__ unsigned ld_acquire(const unsigned* p) {
    unsigned v;
    asm volatile("ld.global.acquire.gpu.u32 %0, [%1];" : "=r"(v) : "l"(p) : "memory");
    return v;
}

__global__ void __launch_bounds__(THREADS, 1)
gru_scan_kernel(const float* __restrict__ x,
                const float* __restrict__ Wih,
                const float* __restrict__ Whh,
                const float* __restrict__ bih,
                const float* __restrict__ bhh,
                float* __restrict__ outbuf)
{
    extern __shared__ float smem[];
    const int tid = threadIdx.x;
    const int cta = blockIdx.x;
    const int grp = cta >> 3;          // batch group 0..15
    const int slc = cta & 7;           // hidden slice 0..7
    const int b0  = grp * NB;
    const int u0  = slc * NU;

    float* sW   = smem + OFF_W;
    float* sBR  = smem + OFF_BR;
    float* sBZ  = smem + OFF_BZ;
    float* sBIN = smem + OFF_BIN;
    float* sBHN = smem + OFF_BHN;
    float* sX   = smem + OFF_X;
    float* sH   = smem + OFF_H;
    float* sPx  = smem + OFF_PX;
    float* sPh  = smem + OFF_PH;

    float* hid = outbuf + (size_t)B * T;   // hiddens region [B][T][H]

    // ---- one-time: load W slice (W_ih | W_hh combined K=384) into SMEM, xor-swizzled ----
    for (int rk = tid; rk < 96 * 384; rk += THREADS) {
        int row  = rk / 384;            // gate*32 + u
        int k    = rk % 384;            // combined K
        int gate = row >> 5;
        int u    = row & 31;
        int R    = gate * 256 + u0 + u; // global gate-row
        float v  = (k < 128) ? Wih[(size_t)R * I + k]
                             : Whh[(size_t)R * H + (k - 128)];
        sW[(gate * 384 + k) * 32 + (u ^ (k & 31))] = v;
    }
    if (tid < 32) {
        int u = tid;
        sBR[u]  = bih[0 * 256 + u0 + u] + bhh[0 * 256 + u0 + u];
        sBZ[u]  = bih[1 * 256 + u0 + u] + bhh[1 * 256 + u0 + u];
        sBIN[u] = bih[2 * 256 + u0 + u];
        sBHN[u] = bhh[2 * 256 + u0 + u];
    }
    // preload x_0 into buffer 0
    {
        int b = tid >> 6;
        int c = (tid & 63) * 2;
        float2 v = *reinterpret_cast<const float2*>(&x[((size_t)(b0 + b) * T + 0) * I + c]);
        *reinterpret_cast<float2*>(&sX[0 * NB * I + b * I + c]) = v;
    }
    __syncthreads();

    const int u  = tid & 31;
    const int ks = tid >> 5;
    const unsigned* flagp = &g_flags[grp];

    for (int t = 0; t < T; ++t) {
        const float* xb = sX + (t & 1) * NB * I;

        // ---- x-phase (independent of h; overlaps barrier latency) ----
        float ax[3][4];
        #pragma unroll
        for (int gg = 0; gg < 3; ++gg)
            #pragma unroll
            for (int bb = 0; bb < 4; ++bb) ax[gg][bb] = 0.f;

        #pragma unroll
        for (int kk = 0; kk < 16; ++kk) {
            int k = ks * 16 + kk;
            int sw = (u ^ (k & 31));
            float w0 = sW[(0 * 384 + k) * 32 + sw];
            float w1 = sW[(1 * 384 + k) * 32 + sw];
            float w2 = sW[(2 * 384 + k) * 32 + sw];
            float x0 = xb[0 * I + k];
            float x1 = xb[1 * I + k];
            float x2 = xb[2 * I + k];
            float x3 = xb[3 * I + k];
            ax[0][0] += w0 * x0; ax[0][1] += w0 * x1; ax[0][2] += w0 * x2; ax[0][3] += w0 * x3;
            ax[1][0] += w1 * x0; ax[1][1] += w1 * x1; ax[1][2] += w1 * x2; ax[1][3] += w1 * x3;
            ax[2][0] += w2 * x0; ax[2][1] += w2 * x1; ax[2][2] += w2 * x2; ax[2][3] += w2 * x3;
        }
        #pragma unroll
        for (int gg = 0; gg < 3; ++gg)
            #pragma unroll
            for (int bb = 0; bb < 4; ++bb)
                sPx[((gg * 4 + bb) * KSPL + ks) * 32 + u] = ax[gg][bb];

        // prefetch x_{t+1} into the other buffer (lands before next-iter sync)
        if (t + 1 < T) {
            int b = tid >> 6;
            int c = (tid & 63) * 2;
            float2 v = *reinterpret_cast<const float2*>(&x[((size_t)(b0 + b) * T + (t + 1)) * I + c]);
            *reinterpret_cast<float2*>(&sX[((t + 1) & 1) * NB * I + b * I + c]) = v;
        }

        if (t > 0) {
            // wait until all 8 slices of this group published h_{t-1}
            if (tid == 0) {
                unsigned target = (unsigned)(NS * t);
                while (ld_acquire(flagp) < target) { }
            }
            __syncthreads();
            // load h_{t-1} for our 4 batches
            {
                int b = tid >> 6;
                int c = (tid & 63) * 4;
                float4 v = *reinterpret_cast<const float4*>(
                    &hid[((size_t)(b0 + b) * T + (t - 1)) * H + c]);
                *reinterpret_cast<float4*>(&sH[b * H + c]) = v;
            }
            __syncthreads();

            // ---- h-phase ----
            float ah[3][4];
            #pragma unroll
            for (int gg = 0; gg < 3; ++gg)
                #pragma unroll
                for (int bb = 0; bb < 4; ++bb) ah[gg][bb] = 0.f;

            #pragma unroll
            for (int kk = 0; kk < 32; ++kk) {
                int kh = ks * 32 + kk;
                int k  = 128 + kh;
                int sw = (u ^ (k & 31));
                float w0 = sW[(0 * 384 + k) * 32 + sw];
                float w1 = sW[(1 * 384 + k) * 32 + sw];
                float w2 = sW[(2 * 384 + k) * 32 + sw];
                float h0 = sH[0 * H + kh];
                float h1 = sH[1 * H + kh];
                float h2 = sH[2 * H + kh];
                float h3 = sH[3 * H + kh];
                ah[0][0] += w0 * h0; ah[0][1] += w0 * h1; ah[0][2] += w0 * h2; ah[0][3] += w0 * h3;
                ah[1][0] += w1 * h0; ah[1][1] += w1 * h1; ah[1][2] += w1 * h2; ah[1][3] += w1 * h3;
                ah[2][0] += w2 * h0; ah[2][1] += w2 * h1; ah[2][2] += w2 * h2; ah[2][3] += w2 * h3;
            }
            #pragma unroll
            for (int gg = 0; gg < 3; ++gg)
                #pragma unroll
                for (int bb = 0; bb < 4; ++bb)
                    sPh[((gg * 4 + bb) * KSPL + ks) * 32 + u] = ah[gg][bb];
        }
        __syncthreads();   // Px (+Ph, +sH) visible to combine threads

        // ---- combine: gates + state update, 128 threads = (u, b) pairs ----
        if (tid < 128) {
            int uu = tid & 31;
            int bb = tid >> 5;
            float sx0 = 0.f, sx1 = 0.f, sx2 = 0.f;
            float sh0 = 0.f, sh1 = 0.f, sh2 = 0.f;
            #pragma unroll
            for (int kq = 0; kq < KSPL; ++kq) {
                sx0 += sPx[((0 * 4 + bb) * KSPL + kq) * 32 + uu];
                sx1 += sPx[((1 * 4 + bb) * KSPL + kq) * 32 + uu];
                sx2 += sPx[((2 * 4 + bb) * KSPL + kq) * 32 + uu];
            }
            float hprev = 0.f;
            if (t > 0) {
                #pragma unroll
                for (int kq = 0; kq < KSPL; ++kq) {
                    sh0 += sPh[((0 * 4 + bb) * KSPL + kq) * 32 + uu];
                    sh1 += sPh[((1 * 4 + bb) * KSPL + kq) * 32 + uu];
                    sh2 += sPh[((2 * 4 + bb) * KSPL + kq) * 32 + uu];
                }
                hprev = sH[bb * H + u0 + uu];
            }
            float pre_r = sx0 + sh0 + sBR[uu];
            float pre_z = sx1 + sh1 + sBZ[uu];
            float r = 1.f / (1.f + expf(-pre_r));
            float z = 1.f / (1.f + expf(-pre_z));
            float i_n = sx2 + sBIN[uu];
            float h_n = sh2 + sBHN[uu];
            float n = tanhf(i_n + r * h_n);
            float hnew = (1.f - z) * n + z * hprev;
            hid[((size_t)(b0 + bb) * T + t) * H + u0 + uu] = hnew;
        }
        __syncthreads();
        if (tid == 0) {
            __threadfence();
            atomicAdd((unsigned*)flagp, 1u);   // publish h_t for this slice
        }
    }
}

// outputs[b,t] = hiddens[b,t,:] . W_o + b_o ; also resets barrier flags for replay determinism
__global__ void gru_out_kernel(const float* __restrict__ Wo,
                               const float* __restrict__ bo,
                               float* __restrict__ outbuf)
{
    if (blockIdx.x == 0 && threadIdx.x < NG) g_flags[threadIdx.x] = 0u;

    int gw   = (int)((blockIdx.x * blockDim.x + threadIdx.x) >> 5);  // one warp per (b,t)
    int lane = threadIdx.x & 31;
    if (gw >= B * T) return;

    const float* hrow = outbuf + (size_t)B * T + (size_t)gw * H;
    float s = 0.f;
    #pragma unroll
    for (int c = 0; c < 8; ++c) {
        int k = c * 32 + lane;
        s += hrow[k] * __ldg(&Wo[k]);
    }
    #pragma unroll
    for (int off = 16; off; off >>= 1)
        s += __shfl_xor_sync(0xffffffffu, s, off);
    if (lane == 0) outbuf[gw] = s + __ldg(&bo[0]);
}

extern "C" void kernel_launch(void* const* d_in, const int* in_sizes, int n_in,
                              void* d_out, int out_size)
{
    const float* x   = (const float*)d_in[0];
    const float* Wih = (const float*)d_in[1];
    const float* Whh = (const float*)d_in[2];
    const float* bih = (const float*)d_in[3];
    const float* bhh = (const float*)d_in[4];
    const float* Wo  = (const float*)d_in[5];
    const float* bo  = (const float*)d_in[6];
    float* out = (float*)d_out;

    cudaFuncSetAttribute(gru_scan_kernel,
                         cudaFuncAttributeMaxDynamicSharedMemorySize, SMEM_BYTES);

    gru_scan_kernel<<<NG * NS, THREADS, SMEM_BYTES>>>(x, Wih, Whh, bih, bhh, out);
    gru_out_kernel<<<(B * T * 32) / 256, 256>>>(Wo, bo, out);
}